// round 14
// baseline (speedup 1.0000x reference)
#include <cuda_runtime.h>
#include <cstring>

#define VOCAB 512
#define EMBD  128
#define HID   64
#define BATCH 256
#define TLEN  1024

// Precomputed layer-0 input table: P0[v][j] = bih0[j] + bhh0[j] + emb[v] . Wih0[j]
__device__ float g_P0[VOCAB * HID];

// ---------------------------------------------------------------------------
// Kernel 1: precompute P0 (512 x 64, each a 128-dot). Trivial cost.
// ---------------------------------------------------------------------------
__global__ void precompute_P0(const float* __restrict__ emb,
                              const float* __restrict__ Wih0,
                              const float* __restrict__ bih0,
                              const float* __restrict__ bhh0)
{
    __shared__ float embs[EMBD];
    __shared__ float ws[HID * (EMBD + 1)];
    const int v = blockIdx.x;
    const int j = threadIdx.x;               // 64 threads

    embs[j]      = emb[v * EMBD + j];
    embs[j + 64] = emb[v * EMBD + j + 64];
    for (int r = 0; r < HID; r++) {
        ws[r * (EMBD + 1) + j]      = Wih0[r * EMBD + j];
        ws[r * (EMBD + 1) + j + 64] = Wih0[r * EMBD + j + 64];
    }
    __syncthreads();

    float acc = bih0[j] + bhh0[j];
    #pragma unroll
    for (int k = 0; k < EMBD; k++)
        acc += embs[k] * ws[j * (EMBD + 1) + k];
    g_P0[v * HID + j] = acc;
}

// ---------------------------------------------------------------------------
// Packed f32x2 helpers (Blackwell FFMA2 / FADD2 — PTX-only)
// ---------------------------------------------------------------------------
__device__ __forceinline__ void ffma2(unsigned long long& d,
                                      unsigned long long a,
                                      unsigned long long b)
{
    asm("fma.rn.f32x2 %0, %1, %2, %0;" : "+l"(d) : "l"(a), "l"(b));
}

__device__ __forceinline__ unsigned long long fadd2(unsigned long long a,
                                                    unsigned long long b)
{
    unsigned long long d;
    asm("add.rn.f32x2 %0, %1, %2;" : "=l"(d) : "l"(a), "l"(b));
    return d;
}

__device__ __forceinline__ float hsum2(unsigned long long a)
{
    float2 f;
    memcpy(&f, &a, 8);
    return f.x + f.y;
}

__device__ __forceinline__ unsigned long long pack2(float lo, float hi)
{
    float2 f; f.x = lo; f.y = hi;
    unsigned long long d;
    memcpy(&d, &f, 8);
    return d;
}

__device__ __forceinline__ float tanh_fast(float x)
{
    float y;
    asm("tanh.approx.f32 %0, %1;" : "=f"(y) : "f"(x));
    return y;
}

// ---------------------------------------------------------------------------
// Kernel 2: fused 2-layer RNN scan + head — staggered dual-group, kh-split.
//
// 128 CTAs x 256 threads; CTA owns 2 batches. Group g = tid>>7 (128 threads,
// warps {4g..4g+3}); warp w sits on SMSP w%4, so every SMSP hosts ONE warp
// of EACH group. Groups use independent named barriers; group 1 is launched
// ~200 cycles late (dummy FFMA chain in its first warp) so the two warps on
// each SMSP run phase-shifted — one group's dependency stalls are filled by
// the other group's issue stream (fixes the R3/R10 lockstep failure).
//
// Within a group, thread r: u = r>>1 (hidden unit), kh = r&1 (k-half).
//   a/b pass over h0[p-1] (kh-half, 8 LDS.128 shared):
//       a: Whh0[u][kh] . h0   (16 FFMA2)   b: Wih1[u][kh] . h0 (16 FFMA2)
//   c pass over h1[p-2] (kh-half, 8 LDS.128): Whh1[u][kh] . h1 (16 FFMA2)
//   halves combine via one in-warp shfl_xor(1) per output (lanes 2u,2u+1);
//   kh=0 finalizes h0[p][u] (P0 folded into kh0's a0 init);
//   kh=1 finalizes h1[p-1][u] (c1 folded into kh1's c0 init).
// ---------------------------------------------------------------------------
__global__ __launch_bounds__(256, 1)
void rnn_scan_kernel(const int*   __restrict__ x,
                     const float* __restrict__ Whh0,
                     const float* __restrict__ Wih1,
                     const float* __restrict__ Whh1,
                     const float* __restrict__ bih1,
                     const float* __restrict__ bhh1,
                     const float* __restrict__ W1,
                     const float* __restrict__ b1,
                     const float* __restrict__ W2,
                     const float* __restrict__ b2,
                     float*       __restrict__ out)
{
    extern __shared__ float smem[];
    // layout (floats): P0s[32768] | xs[2*1025 -> pad 2052] | hbuf[512]
    float* P0s  = smem;
    int*   xs   = (int*)(smem + VOCAB * HID);
    float* hbuf = smem + VOCAB * HID + 2052;
    const int XROW = TLEN + 1;

    const int tid  = threadIdx.x;
    const int w    = tid >> 5;
    const int g    = tid >> 7;       // batch group (warps 4g..4g+3)
    const int r    = tid & 127;
    const int u    = r >> 1;         // hidden unit
    const int kh   = r & 1;          // k-half
    const int bidx = blockIdx.x * 2 + g;

    // ---- stage P0 table (float4)
    {
        const float4* srcp = (const float4*)g_P0;
        float4*       dstp = (float4*)P0s;
        for (int i = tid; i < (VOCAB * HID) / 4; i += 256) dstp[i] = srcp[i];
    }
    // ---- stage token rows with sentinel at index TLEN
    for (int i = tid; i < 2 * XROW; i += 256) {
        int b = i / XROW, t = i % XROW;
        int tt = (t < TLEN) ? t : (TLEN - 1);
        xs[i] = x[(blockIdx.x * 2 + b) * TLEN + tt];
    }
    // ---- zero h buffers
    for (int i = tid; i < 512; i += 256) hbuf[i] = 0.0f;

    // ---- per-thread kh-half weights in registers (48 u64 = 96 floats)
    unsigned long long w0p[16], w1p[16], w2p[16];
    {
        const unsigned long long* a  = (const unsigned long long*)(Whh0 + u * HID + kh * 32);
        const unsigned long long* bq = (const unsigned long long*)(Wih1 + u * HID + kh * 32);
        const unsigned long long* c  = (const unsigned long long*)(Whh1 + u * HID + kh * 32);
        #pragma unroll
        for (int k = 0; k < 16; k++) { w0p[k] = a[k]; w1p[k] = bq[k]; w2p[k] = c[k]; }
    }
    // bias folds: kh0 lane carries P0 (masked), kh1 lane carries c1
    const float p0mask = (kh == 0) ? 1.0f : 0.0f;
    const unsigned long long c1init =
        kh ? pack2(bih1[u] + bhh1[u], 0.0f) : 0ull;

    __syncthreads();

    // ---- STAGGER: delay group 1 by ~200 cyc (dummy dependent FFMA chain in
    // its first warp only; the group's first barrier propagates the shift).
    if (w == 4) {
        float z = (float)(xs[0] & 7) * 1e-30f;
        #pragma unroll
        for (int i = 0; i < 50; i++)
            z = fmaf(z, 1.0000001f, 1e-30f);
        if (z == 123.456f) hbuf[511] = z;   // unprovable-false: keeps the chain
    }

    // per-group buffers (floats, rel. to hb): h0 @ {0,64}, h1 @ {128,192}
    float* hb = hbuf + g * 256;
    const int barid = 1 + g;
    const int* xrow = xs + g * XROW;

    // ---- peeled phase 0: h0[0] = tanh(P0[tok0]); h1[-1] stays 0
    if (kh == 0)
        hb[64 + u] = tanh_fast(P0s[xrow[0] * HID + u]);
    float p0v = P0s[xrow[1] * HID + u] * p0mask;   // carried prefetch (masked)
    asm volatile("bar.sync %0, 128;" :: "r"(barid) : "memory");

    int roff = 64;   // phase 1 reads h0[0] at offset 64

    for (int p = 1; p < TLEN; p++) {
        const float* rp = hb + roff;            // h0[p-1] @ rp, h1[p-2] @ rp+128
        float*       wp = hb + (roff ^ 64);     // h0[p] target, h1[p-1] @ +128

        // ---- a/b pass over this thread's kh-half of h0[p-1] (8 x LDS.128)
        unsigned long long a0 = pack2(p0v, 0.0f), a1 = 0, b0 = 0, b1 = 0;
        {
            const ulonglong2* hv2 = (const ulonglong2*)(rp + kh * 32);
            #pragma unroll
            for (int jj = 0; jj < 8; jj++) {
                ulonglong2 v = hv2[jj];
                ffma2(a0, v.x, w0p[2 * jj]);
                ffma2(b0, v.x, w1p[2 * jj]);
                ffma2(a1, v.y, w0p[2 * jj + 1]);
                ffma2(b1, v.y, w1p[2 * jj + 1]);
            }
        }

        // ---- prefetch next phase's P0 (masked for kh1)
        const float p0n = P0s[xrow[p + 1] * HID + u] * p0mask;

        // ---- c pass over kh-half of h1[p-2] (8 x LDS.128); a-chain drains
        unsigned long long c0 = c1init, c1b = 0;
        {
            const ulonglong2* gv2 = (const ulonglong2*)(rp + 128 + kh * 32);
            #pragma unroll
            for (int jj = 0; jj < 8; jj++) {
                ulonglong2 v = gv2[jj];
                ffma2(c0,  v.x, w2p[2 * jj]);
                ffma2(c1b, v.y, w2p[2 * jj + 1]);
            }
        }

        // ---- finalize h0[p]: pair-combine (lanes 2u, 2u+1), kh0 writes
        float r0 = hsum2(fadd2(a0, a1));
        r0 += __shfl_xor_sync(0xffffffffu, r0, 1);
        if (kh == 0)
            wp[u] = tanh_fast(r0);

        // ---- finalize h1[p-1]: kh1 writes (c1 already folded)
        float q = hsum2(fadd2(fadd2(b0, b1), fadd2(c0, c1b)));
        q += __shfl_xor_sync(0xffffffffu, q, 1);
        if (kh == 1)
            wp[128 + u] = tanh_fast(q);

        p0v = p0n;
        roff ^= 64;
        asm volatile("bar.sync %0, 128;" :: "r"(barid) : "memory");
    }

    // ---- peeled phase TLEN: only h1[T-1]; roff==0 here:
    // h0[T-1] @ hb+0, h1[T-2] @ hb+128; kh1 writes hb[192+u].
    {
        unsigned long long b0 = 0, b1 = 0, c0 = c1init, c1b = 0;
        const ulonglong2* hv2 = (const ulonglong2*)(hb + kh * 32);
        const ulonglong2* gv2 = (const ulonglong2*)(hb + 128 + kh * 32);
        #pragma unroll
        for (int jj = 0; jj < 8; jj++) {
            ulonglong2 v = hv2[jj];
            ffma2(b0, v.x, w1p[2 * jj]);
            ffma2(b1, v.y, w1p[2 * jj + 1]);
            ulonglong2 t = gv2[jj];
            ffma2(c0,  t.x, w2p[2 * jj]);
            ffma2(c1b, t.y, w2p[2 * jj + 1]);
        }
        float q = hsum2(fadd2(fadd2(b0, b1), fadd2(c0, c1b)));
        q += __shfl_xor_sync(0xffffffffu, q, 1);
        if (kh == 1)
            hb[192 + u] = tanh_fast(q);
    }
    asm volatile("bar.sync %0, 128;" :: "r"(barid) : "memory");

    const float* h1f = hb + 192;   // h1[T-1]

    // ---- head: y = relu(h1f @ W1^T + b1) @ W2^T + b2  (first warp of group)
    if (r < 32) {
        float acc = b1[r];
        #pragma unroll
        for (int k = 0; k < HID; k++)
            acc += W1[r * HID + k] * h1f[k];
        acc = fmaxf(acc, 0.0f);
        float s = acc * W2[r];
        #pragma unroll
        for (int off = 16; off; off >>= 1)
            s += __shfl_down_sync(0xffffffffu, s, off);
        if (r == 0) out[bidx] = s + b2[0];
    }
}

// ---------------------------------------------------------------------------
extern "C" void kernel_launch(void* const* d_in, const int* in_sizes, int n_in,
                              void* d_out, int out_size)
{
    const int*   x    = (const int*)  d_in[0];
    const float* emb  = (const float*)d_in[1];
    const float* Wih0 = (const float*)d_in[2];
    const float* Whh0 = (const float*)d_in[3];
    const float* bih0 = (const float*)d_in[4];
    const float* bhh0 = (const float*)d_in[5];
    const float* Wih1 = (const float*)d_in[6];
    const float* Whh1 = (const float*)d_in[7];
    const float* bih1 = (const float*)d_in[8];
    const float* bhh1 = (const float*)d_in[9];
    const float* W1   = (const float*)d_in[10];
    const float* b1   = (const float*)d_in[11];
    const float* W2   = (const float*)d_in[12];
    const float* b2   = (const float*)d_in[13];
    float* out = (float*)d_out;

    precompute_P0<<<VOCAB, 64>>>(emb, Wih0, bih0, bhh0);

    const int smem_bytes = (VOCAB * HID + 2052 + 512) * 4;   // 141,312 B
    cudaFuncSetAttribute(rnn_scan_kernel,
                         cudaFuncAttributeMaxDynamicSharedMemorySize, smem_bytes);
    rnn_scan_kernel<<<BATCH / 2, 256, smem_bytes>>>(
        x, Whh0, Wih1, Whh1, bih1, bhh1, W1, b1, W2, b2, out);
}

// round 15
// speedup vs baseline: 1.2843x; 1.2843x over previous
#include <cuda_runtime.h>
#include <cstring>

#define VOCAB 512
#define EMBD  128
#define HID   64
#define BATCH 256
#define TLEN  1024
#define RING  16          // h0 ring slots per group (power of 2)

// Precomputed layer-0 input table: P0[v][j] = bih0[j] + bhh0[j] + emb[v] . Wih0[j]
__device__ float g_P0[VOCAB * HID];

// ---------------------------------------------------------------------------
// Kernel 1: precompute P0 (512 x 64, each a 128-dot). Trivial cost.
// ---------------------------------------------------------------------------
__global__ void precompute_P0(const float* __restrict__ emb,
                              const float* __restrict__ Wih0,
                              const float* __restrict__ bih0,
                              const float* __restrict__ bhh0)
{
    __shared__ float embs[EMBD];
    __shared__ float ws[HID * (EMBD + 1)];
    const int v = blockIdx.x;
    const int j = threadIdx.x;               // 64 threads

    embs[j]      = emb[v * EMBD + j];
    embs[j + 64] = emb[v * EMBD + j + 64];
    for (int r = 0; r < HID; r++) {
        ws[r * (EMBD + 1) + j]      = Wih0[r * EMBD + j];
        ws[r * (EMBD + 1) + j + 64] = Wih0[r * EMBD + j + 64];
    }
    __syncthreads();

    float acc = bih0[j] + bhh0[j];
    #pragma unroll
    for (int k = 0; k < EMBD; k++)
        acc += embs[k] * ws[j * (EMBD + 1) + k];
    g_P0[v * HID + j] = acc;
}

// ---------------------------------------------------------------------------
// Packed f32x2 helpers (Blackwell FFMA2 / FADD2 — PTX-only)
// ---------------------------------------------------------------------------
__device__ __forceinline__ void ffma2(unsigned long long& d,
                                      unsigned long long a,
                                      unsigned long long b)
{
    asm("fma.rn.f32x2 %0, %1, %2, %0;" : "+l"(d) : "l"(a), "l"(b));
}

__device__ __forceinline__ unsigned long long fadd2(unsigned long long a,
                                                    unsigned long long b)
{
    unsigned long long d;
    asm("add.rn.f32x2 %0, %1, %2;" : "=l"(d) : "l"(a), "l"(b));
    return d;
}

__device__ __forceinline__ float hsum2(unsigned long long a)
{
    float2 f;
    memcpy(&f, &a, 8);
    return f.x + f.y;
}

__device__ __forceinline__ unsigned long long pack2(float lo, float hi)
{
    float2 f; f.x = lo; f.y = hi;
    unsigned long long d;
    memcpy(&d, &f, 8);
    return d;
}

__device__ __forceinline__ float tanh_fast(float x)
{
    float y;
    asm("tanh.approx.f32 %0, %1;" : "=f"(y) : "f"(x));
    return y;
}

// ---------------------------------------------------------------------------
// Kernel 2: decoupled producer/consumer RNN scan.
//
// 128 CTAs x 256 threads (8 warps); CTA owns 2 batches.
// Warp roles: {w0,w1}=light g0, {w2,w3}=heavy g0, {w4,w5}=heavy g1,
// {w6,w7}=light g1  ->  every SMSP (w%4) hosts one light + one heavy warp
// of DIFFERENT groups (different code paths: no lockstep attractor).
//
// light pair (64 thr, units u=half*32+lane):
//   runs the whole L0 scan: h0[t] = tanh(P0[tok_t] + Whh0.h0[t-1]);
//   writes h0[t] into ring slot t&15; intra-pair bar; u==0 sets flag[slot]=t.
//   Backpressure: waits until heavy has consumed t-RING (hv >= t-RING).
// heavy pair: runs the L1 scan: h1[t] = tanh(Wih1.h0[t] + Whh1.h1[t-1] + c1);
//   spins (rarely) on flag[t&15]==t, reads the ring slot, double-buffered h1;
//   intra-pair bar; u==0 publishes hv=t (slot consumable).
// No cross-layer barrier at all — the per-phase coupling of R2..R12 is gone.
// ---------------------------------------------------------------------------
__global__ __launch_bounds__(256, 1)
void rnn_scan_kernel(const int*   __restrict__ x,
                     const float* __restrict__ Whh0,
                     const float* __restrict__ Wih1,
                     const float* __restrict__ Whh1,
                     const float* __restrict__ bih1,
                     const float* __restrict__ bhh1,
                     const float* __restrict__ W1,
                     const float* __restrict__ b1,
                     const float* __restrict__ W2,
                     const float* __restrict__ b2,
                     float*       __restrict__ out)
{
    extern __shared__ float smem[];
    // floats: P0s[32768] | xs(int)[2*1025 -> 2052] | 2 x group block[1184]
    //   group block: ring[RING*64]=1024 | h1db[128] | flags[16 int] | hv | pad
    float* P0s = smem;
    int*   xs  = (int*)(smem + VOCAB * HID);
    float* gmem0 = smem + VOCAB * HID + 2052;
    const int GSTRIDE = RING * 64 + 128 + 32;   // 1184 floats
    const int XROW = TLEN + 1;

    const int tid  = threadIdx.x;
    const int w    = tid >> 5;
    const int lane = tid & 31;
    const int g    = w >> 2;                       // batch group
    const bool light = (((w + 2) & 7) < 4);        // w in {0,1,6,7}
    const int half = w & 1;
    const int u    = half * 32 + lane;
    const int bidx = blockIdx.x * 2 + g;

    // ---- stage P0 (float4), tokens (sentinel at TLEN), init comm blocks
    {
        const float4* srcp = (const float4*)g_P0;
        float4*       dstp = (float4*)P0s;
        for (int i = tid; i < (VOCAB * HID) / 4; i += 256) dstp[i] = srcp[i];
    }
    for (int i = tid; i < 2 * XROW; i += 256) {
        int b = i / XROW, t = i % XROW;
        int tt = (t < TLEN) ? t : (TLEN - 1);
        xs[i] = x[(blockIdx.x * 2 + b) * TLEN + tt];
    }
    for (int gg = 0; gg < 2; gg++) {
        float* gf = gmem0 + gg * GSTRIDE;
        for (int i = tid; i < 128; i += 256) gf[RING * 64 + i] = 0.0f;  // h1db
        int* fl = (int*)(gf + RING * 64 + 128);
        for (int i = tid; i < 17; i += 256) fl[i] = -1;                 // flags+hv
    }
    __syncthreads();

    float* gf    = gmem0 + g * GSTRIDE;
    float* ring  = gf;
    float* h1db  = gf + RING * 64;
    volatile int* flags = (volatile int*)(gf + RING * 64 + 128);
    volatile int* hv    = flags + 16;
    const int* xrow = xs + g * XROW;
    const int barid = 1 + (g * 2) + (light ? 0 : 1);   // 1..4

    if (light) {
        // ================= LIGHT: layer-0 producer ========================
        unsigned long long w0p[32];
        {
            const unsigned long long* a = (const unsigned long long*)(Whh0 + u * HID);
            #pragma unroll
            for (int k = 0; k < 32; k++) w0p[k] = a[k];
        }

        // t = 0 (peeled): h0[0] = tanh(P0[tok0])
        ring[0 * 64 + u] = tanh_fast(P0s[xrow[0] * HID + u]);
        float p0v = P0s[xrow[1] * HID + u];
        asm volatile("bar.sync %0, 64;" :: "r"(barid) : "memory");
        if (u == 0) flags[0] = 0;

        for (int t = 1; t < TLEN; t++) {
            // h0[t-1] lives in slot (t-1)&15 (safe: overwritten only at t-1+RING)
            const ulonglong2* hv2 =
                (const ulonglong2*)(ring + ((t - 1) & (RING - 1)) * 64);
            unsigned long long a0 = pack2(p0v, 0.0f), a1 = 0, a2 = 0, a3 = 0;
            #pragma unroll
            for (int jj = 0; jj < 16; jj += 2) {
                ulonglong2 v0 = hv2[jj];
                ffma2(a0, v0.x, w0p[2 * jj]);
                ffma2(a1, v0.y, w0p[2 * jj + 1]);
                ulonglong2 v1 = hv2[jj + 1];
                ffma2(a2, v1.x, w0p[2 * jj + 2]);
                ffma2(a3, v1.y, w0p[2 * jj + 3]);
            }
            const float p0n = P0s[xrow[t + 1] * HID + u];   // sentinel-safe
            const float val = tanh_fast(hsum2(fadd2(fadd2(a0, a1), fadd2(a2, a3))));

            // backpressure: slot t&15 holds h0[t-RING]; wait until consumed
            while (*hv < t - RING) { __nanosleep(32); }
            asm volatile("" ::: "memory");

            ring[(t & (RING - 1)) * 64 + u] = val;
            asm volatile("bar.sync %0, 64;" :: "r"(barid) : "memory");
            if (u == 0) flags[t & (RING - 1)] = t;
            p0v = p0n;
        }
    } else {
        // ================= HEAVY: layer-1 consumer ========================
        unsigned long long w1p[32], w2p[32];
        {
            const unsigned long long* bq = (const unsigned long long*)(Wih1 + u * HID);
            const unsigned long long* c  = (const unsigned long long*)(Whh1 + u * HID);
            #pragma unroll
            for (int k = 0; k < 32; k++) { w1p[k] = bq[k]; w2p[k] = c[k]; }
        }
        const unsigned long long c1init = pack2(bih1[u] + bhh1[u], 0.0f);

        for (int t = 0; t < TLEN; t++) {
            const int s = t & (RING - 1);
            while (flags[s] != t) { }          // producer is normally ahead
            asm volatile("" ::: "memory");

            // L1a over h0[t] (ring slot s)
            const ulonglong2* hp = (const ulonglong2*)(ring + s * 64);
            unsigned long long b0 = 0, b1 = 0, b2 = 0, b3 = 0;
            #pragma unroll
            for (int jj = 0; jj < 16; jj += 2) {
                ulonglong2 v0 = hp[jj];
                ffma2(b0, v0.x, w1p[2 * jj]);
                ffma2(b1, v0.y, w1p[2 * jj + 1]);
                ulonglong2 v1 = hp[jj + 1];
                ffma2(b2, v1.x, w1p[2 * jj + 2]);
                ffma2(b3, v1.y, w1p[2 * jj + 3]);
            }
            // L1b over h1[t-1] (double buffer (t+1)&1)
            const ulonglong2* gp = (const ulonglong2*)(h1db + ((t + 1) & 1) * 64);
            unsigned long long c0 = c1init, c1b = 0, c2 = 0, c3 = 0;
            #pragma unroll
            for (int jj = 0; jj < 16; jj += 2) {
                ulonglong2 v0 = gp[jj];
                ffma2(c0,  v0.x, w2p[2 * jj]);
                ffma2(c1b, v0.y, w2p[2 * jj + 1]);
                ulonglong2 v1 = gp[jj + 1];
                ffma2(c2,  v1.x, w2p[2 * jj + 2]);
                ffma2(c3,  v1.y, w2p[2 * jj + 3]);
            }
            const unsigned long long sb = fadd2(fadd2(b0, b1), fadd2(b2, b3));
            const unsigned long long sc = fadd2(fadd2(c0, c1b), fadd2(c2, c3));
            h1db[(t & 1) * 64 + u] = tanh_fast(hsum2(fadd2(sb, sc)));

            // bar: both heavy warps done reading slot s and writing h1[t]
            asm volatile("bar.sync %0, 64;" :: "r"(barid) : "memory");
            if (u == 0) *hv = t;
        }

        // ---- head (heavy half-0 warp of each group); h1[T-1] in db[1]
        if (half == 0) {
            const float* h1f = h1db + 64;
            float acc = b1[lane];
            #pragma unroll
            for (int k = 0; k < HID; k++)
                acc += W1[lane * HID + k] * h1f[k];
            acc = fmaxf(acc, 0.0f);
            float sacc = acc * W2[lane];
            #pragma unroll
            for (int off = 16; off; off >>= 1)
                sacc += __shfl_down_sync(0xffffffffu, sacc, off);
            if (lane == 0) out[bidx] = sacc + b2[0];
        }
    }
}

// ---------------------------------------------------------------------------
extern "C" void kernel_launch(void* const* d_in, const int* in_sizes, int n_in,
                              void* d_out, int out_size)
{
    const int*   x    = (const int*)  d_in[0];
    const float* emb  = (const float*)d_in[1];
    const float* Wih0 = (const float*)d_in[2];
    const float* Whh0 = (const float*)d_in[3];
    const float* bih0 = (const float*)d_in[4];
    const float* bhh0 = (const float*)d_in[5];
    const float* Wih1 = (const float*)d_in[6];
    const float* Whh1 = (const float*)d_in[7];
    const float* bih1 = (const float*)d_in[8];
    const float* bhh1 = (const float*)d_in[9];
    const float* W1   = (const float*)d_in[10];
    const float* b1   = (const float*)d_in[11];
    const float* W2   = (const float*)d_in[12];
    const float* b2   = (const float*)d_in[13];
    float* out = (float*)d_out;

    precompute_P0<<<VOCAB, 64>>>(emb, Wih0, bih0, bhh0);

    // floats: P0 32768 + xs 2052 + 2 * 1184
    const int smem_bytes = (VOCAB * HID + 2052 + 2 * (RING * 64 + 128 + 32)) * 4;
    cudaFuncSetAttribute(rnn_scan_kernel,
                         cudaFuncAttributeMaxDynamicSharedMemorySize, smem_bytes);
    rnn_scan_kernel<<<BATCH / 2, 256, smem_bytes>>>(
        x, Whh0, Wih1, Whh1, bih1, bhh1, W1, b1, W2, b2, out);
}

// round 16
// speedup vs baseline: 1.4255x; 1.1100x over previous
#include <cuda_runtime.h>
#include <cstring>

#define VOCAB 512
#define EMBD  128
#define HID   64
#define BATCH 256
#define TLEN  1024
#define RING  16          // h0 ring slots per group (power of 2)

// Precomputed layer-0 input table: P0[v][j] = bih0[j] + bhh0[j] + emb[v] . Wih0[j]
__device__ float g_P0[VOCAB * HID];

// ---------------------------------------------------------------------------
// Kernel 1: precompute P0 (512 x 64, each a 128-dot). Trivial cost.
// ---------------------------------------------------------------------------
__global__ void precompute_P0(const float* __restrict__ emb,
                              const float* __restrict__ Wih0,
                              const float* __restrict__ bih0,
                              const float* __restrict__ bhh0)
{
    __shared__ float embs[EMBD];
    __shared__ float ws[HID * (EMBD + 1)];
    const int v = blockIdx.x;
    const int j = threadIdx.x;               // 64 threads

    embs[j]      = emb[v * EMBD + j];
    embs[j + 64] = emb[v * EMBD + j + 64];
    for (int r = 0; r < HID; r++) {
        ws[r * (EMBD + 1) + j]      = Wih0[r * EMBD + j];
        ws[r * (EMBD + 1) + j + 64] = Wih0[r * EMBD + j + 64];
    }
    __syncthreads();

    float acc = bih0[j] + bhh0[j];
    #pragma unroll
    for (int k = 0; k < EMBD; k++)
        acc += embs[k] * ws[j * (EMBD + 1) + k];
    g_P0[v * HID + j] = acc;
}

// ---------------------------------------------------------------------------
// Packed f32x2 helpers (Blackwell FFMA2 / FADD2 — PTX-only)
// ---------------------------------------------------------------------------
__device__ __forceinline__ void ffma2(unsigned long long& d,
                                      unsigned long long a,
                                      unsigned long long b)
{
    asm("fma.rn.f32x2 %0, %1, %2, %0;" : "+l"(d) : "l"(a), "l"(b));
}

__device__ __forceinline__ unsigned long long fadd2(unsigned long long a,
                                                    unsigned long long b)
{
    unsigned long long d;
    asm("add.rn.f32x2 %0, %1, %2;" : "=l"(d) : "l"(a), "l"(b));
    return d;
}

__device__ __forceinline__ float hsum2(unsigned long long a)
{
    float2 f;
    memcpy(&f, &a, 8);
    return f.x + f.y;
}

__device__ __forceinline__ unsigned long long pack2(float lo, float hi)
{
    float2 f; f.x = lo; f.y = hi;
    unsigned long long d;
    memcpy(&d, &f, 8);
    return d;
}

__device__ __forceinline__ float tanh_fast(float x)
{
    float y;
    asm("tanh.approx.f32 %0, %1;" : "=f"(y) : "f"(x));
    return y;
}

// ---------------------------------------------------------------------------
// Kernel 2: decoupled producer/consumer RNN scan — amortized handshake.
//
// 128 CTAs x 256 threads (8 warps); CTA owns 2 batches.
// Warp roles: {w0,w1}=light g0, {w2,w3}=heavy g0, {w4,w5}=heavy g1,
// {w6,w7}=light g1  ->  every SMSP (w%4) hosts one light + one heavy warp
// of DIFFERENT groups (different code paths: no lockstep attractor).
//
// light pair: L0 scan h0[t] = tanh(P0[tok_t] + Whh0.h0[t-1]) into a 16-slot
//   ring; publishes progress lp=t each step; checks backpressure only every
//   8 steps (hv >= t-9 — strictly stronger than the per-step t-16 bound).
// heavy pair: L1 scan h1[t] = tanh(Wih1.h0[t] + Whh1.h1[t-1] + c1);
//   checks availability only every 8 steps (lp >= t+7 validates the whole
//   batch); c-pass (the true serial chain) issues FIRST after the bar;
//   publishes hv=t each step.
// Protocol cost drops from ~130 cyc/step (R14 per-step spins) to ~15.
// ---------------------------------------------------------------------------
__global__ __launch_bounds__(256, 1)
void rnn_scan_kernel(const int*   __restrict__ x,
                     const float* __restrict__ Whh0,
                     const float* __restrict__ Wih1,
                     const float* __restrict__ Whh1,
                     const float* __restrict__ bih1,
                     const float* __restrict__ bhh1,
                     const float* __restrict__ W1,
                     const float* __restrict__ b1,
                     const float* __restrict__ W2,
                     const float* __restrict__ b2,
                     float*       __restrict__ out)
{
    extern __shared__ float smem[];
    // floats: P0s[32768] | xs(int)[2*1025 -> 2052] | 2 x group block
    //   group block: ring[RING*64]=1024 | h1db[128] | ctr[8 int] (lp, hv)
    float* P0s = smem;
    int*   xs  = (int*)(smem + VOCAB * HID);
    float* gmem0 = smem + VOCAB * HID + 2052;
    const int GSTRIDE = RING * 64 + 128 + 8;
    const int XROW = TLEN + 1;

    const int tid  = threadIdx.x;
    const int w    = tid >> 5;
    const int lane = tid & 31;
    const int g    = w >> 2;                       // batch group
    const bool light = (((w + 2) & 7) < 4);        // w in {0,1,6,7}
    const int half = w & 1;
    const int u    = half * 32 + lane;
    const int bidx = blockIdx.x * 2 + g;

    // ---- stage P0 (float4), tokens (sentinel at TLEN), init comm blocks
    {
        const float4* srcp = (const float4*)g_P0;
        float4*       dstp = (float4*)P0s;
        for (int i = tid; i < (VOCAB * HID) / 4; i += 256) dstp[i] = srcp[i];
    }
    for (int i = tid; i < 2 * XROW; i += 256) {
        int b = i / XROW, t = i % XROW;
        int tt = (t < TLEN) ? t : (TLEN - 1);
        xs[i] = x[(blockIdx.x * 2 + b) * TLEN + tt];
    }
    for (int gg = 0; gg < 2; gg++) {
        float* gf = gmem0 + gg * GSTRIDE;
        for (int i = tid; i < 128; i += 256) gf[RING * 64 + i] = 0.0f;  // h1db
        int* fl = (int*)(gf + RING * 64 + 128);
        for (int i = tid; i < 8; i += 256) fl[i] = -1;                  // lp, hv
    }
    __syncthreads();

    float* gf    = gmem0 + g * GSTRIDE;
    float* ring  = gf;
    float* h1db  = gf + RING * 64;
    volatile int* lp = (volatile int*)(gf + RING * 64 + 128);
    volatile int* hv = lp + 1;
    const int* xrow = xs + g * XROW;
    const int barid = 1 + (g * 2) + (light ? 0 : 1);   // 1..4

    if (light) {
        // ================= LIGHT: layer-0 producer ========================
        unsigned long long w0p[32];
        {
            const unsigned long long* a = (const unsigned long long*)(Whh0 + u * HID);
            #pragma unroll
            for (int k = 0; k < 32; k++) w0p[k] = a[k];
        }

        // t = 0 (peeled): h0[0] = tanh(P0[tok0])
        ring[0 * 64 + u] = tanh_fast(P0s[xrow[0] * HID + u]);
        float p0v = P0s[xrow[1] * HID + u];
        asm volatile("bar.sync %0, 64;" :: "r"(barid) : "memory");
        if (u == 0) *lp = 0;

        for (int t = 1; t < TLEN; t++) {
            // batched backpressure: validates writes t..t+7 (overwrite slots
            // of t-16..t-9, all consumed once hv >= t-9)
            if ((t & 7) == 0 && t >= 16) {
                while (*hv < t - 9) { __nanosleep(32); }
                asm volatile("" ::: "memory");
            }

            const ulonglong2* hv2 =
                (const ulonglong2*)(ring + ((t - 1) & (RING - 1)) * 64);
            unsigned long long a0 = pack2(p0v, 0.0f), a1 = 0, a2 = 0, a3 = 0;
            #pragma unroll
            for (int jj = 0; jj < 16; jj += 2) {
                ulonglong2 v0 = hv2[jj];
                ffma2(a0, v0.x, w0p[2 * jj]);
                ffma2(a1, v0.y, w0p[2 * jj + 1]);
                ulonglong2 v1 = hv2[jj + 1];
                ffma2(a2, v1.x, w0p[2 * jj + 2]);
                ffma2(a3, v1.y, w0p[2 * jj + 3]);
            }
            const float p0n = P0s[xrow[t + 1] * HID + u];   // sentinel-safe
            ring[(t & (RING - 1)) * 64 + u] =
                tanh_fast(hsum2(fadd2(fadd2(a0, a1), fadd2(a2, a3))));
            asm volatile("bar.sync %0, 64;" :: "r"(barid) : "memory");
            if (u == 0) *lp = t;
            p0v = p0n;
        }
    } else {
        // ================= HEAVY: layer-1 consumer ========================
        unsigned long long w1p[32], w2p[32];
        {
            const unsigned long long* bq = (const unsigned long long*)(Wih1 + u * HID);
            const unsigned long long* c  = (const unsigned long long*)(Whh1 + u * HID);
            #pragma unroll
            for (int k = 0; k < 32; k++) { w1p[k] = bq[k]; w2p[k] = c[k]; }
        }
        const unsigned long long c1init = pack2(bih1[u] + bhh1[u], 0.0f);

        for (int t = 0; t < TLEN; t++) {
            // batched availability: lp >= t+7 validates ring slots t..t+7
            if ((t & 7) == 0) {
                while (*lp < t + 7) { }
                asm volatile("" ::: "memory");
            }
            const int s = t & (RING - 1);

            // ---- c-pass FIRST: L1b over h1[t-1] — the serial chain
            const ulonglong2* gp = (const ulonglong2*)(h1db + ((t + 1) & 1) * 64);
            unsigned long long c0 = c1init, c1b = 0, c2 = 0, c3 = 0;
            #pragma unroll
            for (int jj = 0; jj < 16; jj += 2) {
                ulonglong2 v0 = gp[jj];
                ffma2(c0,  v0.x, w2p[2 * jj]);
                ffma2(c1b, v0.y, w2p[2 * jj + 1]);
                ulonglong2 v1 = gp[jj + 1];
                ffma2(c2,  v1.x, w2p[2 * jj + 2]);
                ffma2(c3,  v1.y, w2p[2 * jj + 3]);
            }

            // ---- b-pass: L1a over h0[t] (ring slot s, produced long ago)
            const ulonglong2* hp = (const ulonglong2*)(ring + s * 64);
            unsigned long long b0 = 0, b1 = 0, b2 = 0, b3 = 0;
            #pragma unroll
            for (int jj = 0; jj < 16; jj += 2) {
                ulonglong2 v0 = hp[jj];
                ffma2(b0, v0.x, w1p[2 * jj]);
                ffma2(b1, v0.y, w1p[2 * jj + 1]);
                ulonglong2 v1 = hp[jj + 1];
                ffma2(b2, v1.x, w1p[2 * jj + 2]);
                ffma2(b3, v1.y, w1p[2 * jj + 3]);
            }

            const unsigned long long sb = fadd2(fadd2(b0, b1), fadd2(b2, b3));
            const unsigned long long sc = fadd2(fadd2(c0, c1b), fadd2(c2, c3));
            h1db[(t & 1) * 64 + u] = tanh_fast(hsum2(fadd2(sb, sc)));

            asm volatile("bar.sync %0, 64;" :: "r"(barid) : "memory");
            if (u == 0) *hv = t;
        }

        // ---- head (heavy half-0 warp of each group); h1[T-1] in db[1]
        if (half == 0) {
            const float* h1f = h1db + 64;
            float acc = b1[lane];
            #pragma unroll
            for (int k = 0; k < HID; k++)
                acc += W1[lane * HID + k] * h1f[k];
            acc = fmaxf(acc, 0.0f);
            float sacc = acc * W2[lane];
            #pragma unroll
            for (int off = 16; off; off >>= 1)
                sacc += __shfl_down_sync(0xffffffffu, sacc, off);
            if (lane == 0) out[bidx] = sacc + b2[0];
        }
    }
}

// ---------------------------------------------------------------------------
extern "C" void kernel_launch(void* const* d_in, const int* in_sizes, int n_in,
                              void* d_out, int out_size)
{
    const int*   x    = (const int*)  d_in[0];
    const float* emb  = (const float*)d_in[1];
    const float* Wih0 = (const float*)d_in[2];
    const float* Whh0 = (const float*)d_in[3];
    const float* bih0 = (const float*)d_in[4];
    const float* bhh0 = (const float*)d_in[5];
    const float* Wih1 = (const float*)d_in[6];
    const float* Whh1 = (const float*)d_in[7];
    const float* bih1 = (const float*)d_in[8];
    const float* bhh1 = (const float*)d_in[9];
    const float* W1   = (const float*)d_in[10];
    const float* b1   = (const float*)d_in[11];
    const float* W2   = (const float*)d_in[12];
    const float* b2   = (const float*)d_in[13];
    float* out = (float*)d_out;

    precompute_P0<<<VOCAB, 64>>>(emb, Wih0, bih0, bhh0);

    const int smem_bytes = (VOCAB * HID + 2052 + 2 * (RING * 64 + 128 + 8)) * 4;
    cudaFuncSetAttribute(rnn_scan_kernel,
                         cudaFuncAttributeMaxDynamicSharedMemorySize, smem_bytes);
    rnn_scan_kernel<<<BATCH / 2, 256, smem_bytes>>>(
        x, Whh0, Wih1, Whh1, bih1, bhh1, W1, b1, W2, b2, out);
}

// round 17
// speedup vs baseline: 1.5706x; 1.1018x over previous
#include <cuda_runtime.h>
#include <cstring>

#define VOCAB 512
#define EMBD  128
#define HID   64
#define BATCH 256
#define TLEN  1024
#define RING  16          // z-ring slots per group (power of 2)

// Precomputed layer-0 input table: P0[v][j] = bih0[j] + bhh0[j] + emb[v] . Wih0[j]
__device__ float g_P0[VOCAB * HID];

// ---------------------------------------------------------------------------
// Kernel 1: precompute P0 (512 x 64, each a 128-dot). Trivial cost.
// ---------------------------------------------------------------------------
__global__ void precompute_P0(const float* __restrict__ emb,
                              const float* __restrict__ Wih0,
                              const float* __restrict__ bih0,
                              const float* __restrict__ bhh0)
{
    __shared__ float embs[EMBD];
    __shared__ float ws[HID * (EMBD + 1)];
    const int v = blockIdx.x;
    const int j = threadIdx.x;               // 64 threads

    embs[j]      = emb[v * EMBD + j];
    embs[j + 64] = emb[v * EMBD + j + 64];
    for (int r = 0; r < HID; r++) {
        ws[r * (EMBD + 1) + j]      = Wih0[r * EMBD + j];
        ws[r * (EMBD + 1) + j + 64] = Wih0[r * EMBD + j + 64];
    }
    __syncthreads();

    float acc = bih0[j] + bhh0[j];
    #pragma unroll
    for (int k = 0; k < EMBD; k++)
        acc += embs[k] * ws[j * (EMBD + 1) + k];
    g_P0[v * HID + j] = acc;
}

// ---------------------------------------------------------------------------
// Packed f32x2 helpers (Blackwell FFMA2 / FADD2 — PTX-only)
// ---------------------------------------------------------------------------
__device__ __forceinline__ void ffma2(unsigned long long& d,
                                      unsigned long long a,
                                      unsigned long long b)
{
    asm("fma.rn.f32x2 %0, %1, %2, %0;" : "+l"(d) : "l"(a), "l"(b));
}

__device__ __forceinline__ unsigned long long fadd2(unsigned long long a,
                                                    unsigned long long b)
{
    unsigned long long d;
    asm("add.rn.f32x2 %0, %1, %2;" : "=l"(d) : "l"(a), "l"(b));
    return d;
}

__device__ __forceinline__ float hsum2(unsigned long long a)
{
    float2 f;
    memcpy(&f, &a, 8);
    return f.x + f.y;
}

__device__ __forceinline__ unsigned long long pack2(float lo, float hi)
{
    float2 f; f.x = lo; f.y = hi;
    unsigned long long d;
    memcpy(&d, &f, 8);
    return d;
}

__device__ __forceinline__ float tanh_fast(float x)
{
    float y;
    asm("tanh.approx.f32 %0, %1;" : "=f"(y) : "f"(x));
    return y;
}

// ---------------------------------------------------------------------------
// Kernel 2: rebalanced producer/consumer RNN scan.
//
// 128 CTAs x 256 threads; CTA owns 2 batches.
// Warps: {w0,w1}=light g0, {w2,w3}=heavy g0, {w4,w5}=heavy g1,
// {w6,w7}=light g1 -> every SMSP hosts one light + one heavy of DIFFERENT
// groups (no lockstep; complementary code).
//
// light pair (thread u owns unit u, Whh0[u]+Wih1[u] rows in regs):
//   step t: h0[t] = tanh(P0[tok_t] + Whh0.h0[t-1])      (serial chain)
//           z[t-1] = Wih1.h0[t-1]                        (stall filler,
//                shares the 8 LDS.128 of the a-pass; written to z-ring)
//   bar; u==0 publishes lp=t. Backpressure every 8 steps: hv >= t-10.
// heavy pair (thread u owns unit u, Whh1[u] row in regs):
//   step t: h1[t] = tanh(z[t] + c1 + Whh1.h1[t-1])       (the irreducible
//                serial core: 1 LDS + 8 LDS.128 + 32 FFMA2 + tanh)
//   bar; u==0 publishes hv=t. Availability every 8 steps: lp >= t+8
//   (nanosleep while waiting — heavy is the faster stage; don't steal
//   issue slots from the co-resident light warp).
// ---------------------------------------------------------------------------
__global__ __launch_bounds__(256, 1)
void rnn_scan_kernel(const int*   __restrict__ x,
                     const float* __restrict__ Whh0,
                     const float* __restrict__ Wih1,
                     const float* __restrict__ Whh1,
                     const float* __restrict__ bih1,
                     const float* __restrict__ bhh1,
                     const float* __restrict__ W1,
                     const float* __restrict__ b1,
                     const float* __restrict__ W2,
                     const float* __restrict__ b2,
                     float*       __restrict__ out)
{
    extern __shared__ float smem[];
    // floats: P0s[32768] | xs(int)[2*1026 -> 2052] | 2 x group block[1288]
    //   group block: h0db[128] | zring[RING*64=1024] | h1db[128] | ctrs[8]
    float* P0s = smem;
    int*   xs  = (int*)(smem + VOCAB * HID);
    float* gmem0 = smem + VOCAB * HID + 2052;
    const int GSTRIDE = 128 + RING * 64 + 128 + 8;   // 1288 floats
    const int XROW = TLEN + 2;                        // sentinels at 1024,1025

    const int tid  = threadIdx.x;
    const int w    = tid >> 5;
    const int lane = tid & 31;
    const int g    = w >> 2;                       // batch group
    const bool light = (((w + 2) & 7) < 4);        // w in {0,1,6,7}
    const int half = w & 1;
    const int u    = half * 32 + lane;
    const int bidx = blockIdx.x * 2 + g;

    // ---- stage P0 (float4), tokens (sentinels), init comm blocks
    {
        const float4* srcp = (const float4*)g_P0;
        float4*       dstp = (float4*)P0s;
        for (int i = tid; i < (VOCAB * HID) / 4; i += 256) dstp[i] = srcp[i];
    }
    for (int i = tid; i < 2 * XROW; i += 256) {
        int b = i / XROW, t = i % XROW;
        int tt = (t < TLEN) ? t : (TLEN - 1);
        xs[i] = x[(blockIdx.x * 2 + b) * TLEN + tt];
    }
    for (int gg = 0; gg < 2; gg++) {
        float* gf = gmem0 + gg * GSTRIDE;
        for (int i = tid; i < 128; i += 256) {
            gf[i] = 0.0f;                              // h0db
            gf[128 + RING * 64 + i] = 0.0f;            // h1db
        }
        int* fl = (int*)(gf + 128 + RING * 64 + 128);
        for (int i = tid; i < 8; i += 256) fl[i] = -1; // lp, hv
    }
    __syncthreads();

    float* gf    = gmem0 + g * GSTRIDE;
    float* h0db  = gf;
    float* zring = gf + 128;
    float* h1db  = gf + 128 + RING * 64;
    volatile int* lp = (volatile int*)(gf + 128 + RING * 64 + 128);
    volatile int* hv = lp + 1;
    const int* xrow = xs + g * XROW;
    const int barid = 1 + g * 2 + (light ? 0 : 1);   // 1..4

    if (light) {
        // ================= LIGHT: L0 scan + z precompute ==================
        unsigned long long w0p[32], w1p[32];
        {
            const unsigned long long* a  = (const unsigned long long*)(Whh0 + u * HID);
            const unsigned long long* bq = (const unsigned long long*)(Wih1 + u * HID);
            #pragma unroll
            for (int k = 0; k < 32; k++) { w0p[k] = a[k]; w1p[k] = bq[k]; }
        }

        // t = 0 (peeled): h0[0] = tanh(P0[tok0])
        h0db[0 * 64 + u] = tanh_fast(P0s[xrow[0] * HID + u]);
        float p0v = P0s[xrow[1] * HID + u];
        asm volatile("bar.sync %0, 64;" :: "r"(barid) : "memory");
        // lp stays -1: no z published yet

        for (int t = 1; t <= TLEN; t++) {
            // batched z-ring backpressure (writes z[t-1..t+6] overwrite
            // z[t-17..t-10]; safe once hv >= t-10)
            if ((t & 7) == 0 && t >= 16) {
                while (*hv < t - 10) { __nanosleep(32); }
                asm volatile("" ::: "memory");
            }

            const ulonglong2* hv2 =
                (const ulonglong2*)(h0db + ((t - 1) & 1) * 64);
            unsigned long long a0 = pack2(p0v, 0.0f), a1 = 0, b0 = 0, b1 = 0;
            #pragma unroll
            for (int jj = 0; jj < 16; jj++) {
                ulonglong2 v = hv2[jj];
                ffma2(a0, v.x, w0p[2 * jj]);
                ffma2(b0, v.x, w1p[2 * jj]);
                ffma2(a1, v.y, w0p[2 * jj + 1]);
                ffma2(b1, v.y, w1p[2 * jj + 1]);
            }
            const float p0n = P0s[xrow[t + 1] * HID + u];   // sentinel-safe

            // z[t-1] = Wih1 . h0[t-1]  (no tanh; bias folded in heavy)
            zring[((t - 1) & (RING - 1)) * 64 + u] = hsum2(fadd2(b0, b1));
            // h0[t]
            h0db[(t & 1) * 64 + u] = tanh_fast(hsum2(fadd2(a0, a1)));

            asm volatile("bar.sync %0, 64;" :: "r"(barid) : "memory");
            if (u == 0) *lp = t;     // z[0..t-1] published
            p0v = p0n;
        }
    } else {
        // ================= HEAVY: minimal L1 recurrence ===================
        unsigned long long w2p[32];
        {
            const unsigned long long* c = (const unsigned long long*)(Whh1 + u * HID);
            #pragma unroll
            for (int k = 0; k < 32; k++) w2p[k] = c[k];
        }
        const float c1v = bih1[u] + bhh1[u];

        for (int t = 0; t < TLEN; t++) {
            // batched availability: lp >= min(t+8, TLEN) validates z[t..t+7]
            if ((t & 7) == 0) {
                int need = t + 8; if (need > TLEN) need = TLEN;
                while (*lp < need) { __nanosleep(32); }
                asm volatile("" ::: "memory");
            }

            const float zv = zring[(t & (RING - 1)) * 64 + u];
            const ulonglong2* gp =
                (const ulonglong2*)(h1db + ((t + 1) & 1) * 64);
            unsigned long long c0 = pack2(zv + c1v, 0.0f), c1b = 0, c2 = 0, c3 = 0;
            #pragma unroll
            for (int jj = 0; jj < 16; jj += 2) {
                ulonglong2 v0 = gp[jj];
                ffma2(c0,  v0.x, w2p[2 * jj]);
                ffma2(c1b, v0.y, w2p[2 * jj + 1]);
                ulonglong2 v1 = gp[jj + 1];
                ffma2(c2,  v1.x, w2p[2 * jj + 2]);
                ffma2(c3,  v1.y, w2p[2 * jj + 3]);
            }
            h1db[(t & 1) * 64 + u] =
                tanh_fast(hsum2(fadd2(fadd2(c0, c1b), fadd2(c2, c3))));

            asm volatile("bar.sync %0, 64;" :: "r"(barid) : "memory");
            if (u == 0) *hv = t;
        }

        // ---- head; h1[T-1] in h1db slot (1023&1)=1
        if (half == 0) {
            const float* h1f = h1db + 64;
            float acc = b1[lane];
            #pragma unroll
            for (int k = 0; k < HID; k++)
                acc += W1[lane * HID + k] * h1f[k];
            acc = fmaxf(acc, 0.0f);
            float sacc = acc * W2[lane];
            #pragma unroll
            for (int off = 16; off; off >>= 1)
                sacc += __shfl_down_sync(0xffffffffu, sacc, off);
            if (lane == 0) out[bidx] = sacc + b2[0];
        }
    }
}

// ---------------------------------------------------------------------------
extern "C" void kernel_launch(void* const* d_in, const int* in_sizes, int n_in,
                              void* d_out, int out_size)
{
    const int*   x    = (const int*)  d_in[0];
    const float* emb  = (const float*)d_in[1];
    const float* Wih0 = (const float*)d_in[2];
    const float* Whh0 = (const float*)d_in[3];
    const float* bih0 = (const float*)d_in[4];
    const float* bhh0 = (const float*)d_in[5];
    const float* Wih1 = (const float*)d_in[6];
    const float* Whh1 = (const float*)d_in[7];
    const float* bih1 = (const float*)d_in[8];
    const float* bhh1 = (const float*)d_in[9];
    const float* W1   = (const float*)d_in[10];
    const float* b1   = (const float*)d_in[11];
    const float* W2   = (const float*)d_in[12];
    const float* b2   = (const float*)d_in[13];
    float* out = (float*)d_out;

    precompute_P0<<<VOCAB, 64>>>(emb, Wih0, bih0, bhh0);

    // floats: P0 32768 + xs 2052 + 2 * 1288
    const int smem_bytes = (VOCAB * HID + 2052 + 2 * (128 + RING * 64 + 128 + 8)) * 4;
    cudaFuncSetAttribute(rnn_scan_kernel,
                         cudaFuncAttributeMaxDynamicSharedMemorySize, smem_bytes);
    rnn_scan_kernel<<<BATCH / 2, 256, smem_bytes>>>(
        x, Whh0, Wih1, Whh1, bih1, bhh1, W1, b1, W2, b2, out);
}